// round 10
// baseline (speedup 1.0000x reference)
#include <cuda_runtime.h>
#include <cuda_bf16.h>
#include <cstdint>

#define F_IN 128
#define F_OUT 64
#define MAX_NODES 50000

// Scratch (no runtime allocation allowed)
__device__ float g_hw[(size_t)MAX_NODES * F_OUT]; // h @ (W0+W1), [N][64]

// ---------------------------------------------------------------------------
// TF32 helpers
// ---------------------------------------------------------------------------
__device__ __forceinline__ unsigned cvt_tf32(float x) {
    unsigned r;
    asm("cvt.rna.tf32.f32 %0, %1;" : "=r"(r) : "f"(x));
    return r;
}

#define MMA_TF32(d, a0, a1, a2, a3, b0, b1)                                  \
    asm("mma.sync.aligned.m16n8k8.row.col.f32.tf32.tf32.f32 "                \
        "{%0,%1,%2,%3}, {%4,%5,%6,%7}, {%8,%9}, {%0,%1,%2,%3};"              \
        : "+f"(d[0]), "+f"(d[1]), "+f"(d[2]), "+f"(d[3])                     \
        : "r"(a0), "r"(a1), "r"(a2), "r"(a3), "r"(b0), "r"(b1))

// cp.async helpers
__device__ __forceinline__ unsigned smem_u32(const void* p) {
    return (unsigned)__cvta_generic_to_shared(p);
}
#define CP_ASYNC16(s, g) \
    asm volatile("cp.async.cg.shared.global [%0], [%1], 16;" :: "r"(s), "l"(g))
#define CP_COMMIT() asm volatile("cp.async.commit_group;")
#define CP_WAIT1()  asm volatile("cp.async.wait_group 1;" ::: "memory")

// ---------------------------------------------------------------------------
// Kernel 1: fused TF32 tensor-core GEMM + bias-init (3xTF32, fp32 accuracy)
//   g_hw[N,64] = h[N,128] @ (W0+W1) ;  out[N,64] = bias
// (unchanged from round 8: measured ~21us incl. overhead, rel_err 8e-7)
// ---------------------------------------------------------------------------
#define GR 64
#define KC 32
#define HS_S 36
#define WS_S 72
__global__ void __launch_bounds__(128) gemm_tc_kernel(
        const float* __restrict__ h,
        const float* __restrict__ w,
        const float* __restrict__ bias,
        float* __restrict__ out,
        int n_nodes) {
    __shared__ __align__(16) float hs[GR][HS_S];
    __shared__ __align__(16) float wh[KC][WS_S];
    __shared__ __align__(16) float wl[KC][WS_S];
    __shared__ __align__(16) float bs[F_OUT];

    int tid  = threadIdx.x;
    int lane = tid & 31;
    int warp = tid >> 5;
    int g = lane >> 2;
    int t = lane & 3;
    int row0 = blockIdx.x * GR;
    int wr0  = warp * 16;

    if (tid < F_OUT) bs[tid] = bias[tid];

    float acc[8][4];
    #pragma unroll
    for (int nt = 0; nt < 8; nt++)
        #pragma unroll
        for (int i = 0; i < 4; i++) acc[nt][i] = 0.0f;

    #pragma unroll
    for (int chunk = 0; chunk < F_IN / KC; chunk++) {
        int k0 = chunk * KC;
        __syncthreads();

        #pragma unroll
        for (int i = tid; i < GR * (KC / 4); i += 128) {
            int r = i >> 3;
            int c = i & 7;
            float4 v = make_float4(0.f, 0.f, 0.f, 0.f);
            if (row0 + r < n_nodes)
                v = ((const float4*)(h + (size_t)(row0 + r) * F_IN + k0))[c];
            hs[r][4 * c + 0] = v.x;
            hs[r][4 * c + 1] = v.y;
            hs[r][4 * c + 2] = v.z;
            hs[r][4 * c + 3] = v.w;
        }

        #pragma unroll
        for (int i = tid; i < KC * (F_OUT / 4); i += 128) {
            int k = i >> 4;
            int q = i & 15;
            const float4* w0 = (const float4*)(w + (size_t)(k0 + k) * F_OUT);
            const float4* w1 = (const float4*)(w + (size_t)F_IN * F_OUT + (size_t)(k0 + k) * F_OUT);
            float4 s0 = w0[q], s1 = w1[q];
            float s[4] = {s0.x + s1.x, s0.y + s1.y, s0.z + s1.z, s0.w + s1.w};
            #pragma unroll
            for (int j = 0; j < 4; j++) {
                float hi = __uint_as_float(cvt_tf32(s[j]));
                wh[k][4 * q + j] = hi;
                wl[k][4 * q + j] = s[j] - hi;
            }
        }
        __syncthreads();

        #pragma unroll
        for (int ks = 0; ks < KC; ks += 8) {
            float af0 = hs[wr0 + g][ks + t];
            float af1 = hs[wr0 + g + 8][ks + t];
            float af2 = hs[wr0 + g][ks + t + 4];
            float af3 = hs[wr0 + g + 8][ks + t + 4];
            unsigned ah0 = cvt_tf32(af0), ah1 = cvt_tf32(af1);
            unsigned ah2 = cvt_tf32(af2), ah3 = cvt_tf32(af3);
            unsigned al0 = __float_as_uint(af0 - __uint_as_float(ah0));
            unsigned al1 = __float_as_uint(af1 - __uint_as_float(ah1));
            unsigned al2 = __float_as_uint(af2 - __uint_as_float(ah2));
            unsigned al3 = __float_as_uint(af3 - __uint_as_float(ah3));

            #pragma unroll
            for (int nt = 0; nt < 8; nt++) {
                int n = 8 * nt + g;
                unsigned bh0 = __float_as_uint(wh[ks + t][n]);
                unsigned bh1 = __float_as_uint(wh[ks + t + 4][n]);
                unsigned bl0 = __float_as_uint(wl[ks + t][n]);
                unsigned bl1 = __float_as_uint(wl[ks + t + 4][n]);
                MMA_TF32(acc[nt], ah0, ah1, ah2, ah3, bh0, bh1);
                MMA_TF32(acc[nt], ah0, ah1, ah2, ah3, bl0, bl1);
                MMA_TF32(acc[nt], al0, al1, al2, al3, bh0, bh1);
            }
        }
    }

    int r1 = row0 + wr0 + g;
    int r2 = r1 + 8;
    #pragma unroll
    for (int nt = 0; nt < 8; nt++) {
        int c = 8 * nt + 2 * t;
        float2 bv = make_float2(bs[c], bs[c + 1]);
        if (r1 < n_nodes) {
            *(float2*)&g_hw[(size_t)r1 * F_OUT + c] = make_float2(acc[nt][0], acc[nt][1]);
            *(float2*)&out[(size_t)r1 * F_OUT + c] = bv;
        }
        if (r2 < n_nodes) {
            *(float2*)&g_hw[(size_t)r2 * F_OUT + c] = make_float2(acc[nt][2], acc[nt][3]);
            *(float2*)&out[(size_t)r2 * F_OUT + c] = bv;
        }
    }
}

// ---------------------------------------------------------------------------
// Kernel 2: edge phase, WARP-PRIVATE cp.async double-buffered pipeline.
// Each warp owns its own 2 buffers of 4 edges (1KB ef + 32B idx each) and
// grid-strides over 4-edge batches. NO block-level sync anywhere: per-thread
// cp.async group accounting + __syncwarp only. Processing keeps the measured
// optimum of 2 edges per 16-lane group (2x MLP on the g_hw L2 gather).
// ---------------------------------------------------------------------------
#define WEB 4              // edges per warp-batch
#define NWARPS 8           // warps per block
__global__ void __launch_bounds__(256) edge_kernel(
        const float* __restrict__ ef,
        const int* __restrict__ src,
        const int* __restrict__ dst,
        float* __restrict__ out,
        int n_edges) {
    // per-warp: [2 bufs][4 edges][64 floats] ef, [2 bufs][8] idx (4 src + 4 dst)
    __shared__ __align__(16) float ef_s[NWARPS][2][WEB][F_OUT];  // 16 KB
    __shared__ __align__(16) int   idx_s[NWARPS][2][8];          // 512 B

    int tid  = threadIdx.x;
    int lane = tid & 31;
    int wid  = tid >> 5;          // warp in block
    int grp  = lane >> 4;         // 0/1: which edge-pair this half-warp handles
    int sl   = lane & 15;

    int gwarp = blockIdx.x * NWARPS + wid;
    int wstride = gridDim.x * NWARPS;
    int nb = (n_edges + WEB - 1) / WEB;

    const float4* hw4 = (const float4*)g_hw;

    // ---- stage batch -> buf (warp-collective, cp.async; scalar tail) ----
    // full batch: 4 edges * 64 floats = 64 float4 (2 per lane) + 2x16B idx
    #define STAGE(buf, batch)                                                  \
        do {                                                                   \
            size_t e0_ = (size_t)(batch) * WEB;                                \
            if (e0_ + WEB <= (size_t)n_edges) {                                \
                const char* gef_ = (const char*)(ef + e0_ * F_OUT);            \
                unsigned sef_ = smem_u32(&ef_s[wid][buf][0][0]);               \
                CP_ASYNC16(sef_ + lane * 16, gef_ + lane * 16);                \
                CP_ASYNC16(sef_ + (lane + 32) * 16, gef_ + (lane + 32) * 16);  \
                if (lane == 0)                                                 \
                    CP_ASYNC16(smem_u32(&idx_s[wid][buf][0]),                  \
                               (const char*)(src + e0_));                      \
                if (lane == 1)                                                 \
                    CP_ASYNC16(smem_u32(&idx_s[wid][buf][4]),                  \
                               (const char*)(dst + e0_));                      \
            } else {                                                           \
                for (int f_ = lane; f_ < WEB * (F_OUT / 4); f_ += 32) {        \
                    int e_ = f_ >> 4;                                          \
                    float4 v_ = make_float4(0.f, 0.f, 0.f, 0.f);               \
                    if (e0_ + e_ < (size_t)n_edges)                            \
                        v_ = ((const float4*)(ef + (e0_ + e_) * F_OUT))[f_ & 15]; \
                    *(float4*)&ef_s[wid][buf][e_][4 * (f_ & 15)] = v_;         \
                }                                                              \
                if (lane < WEB) {                                              \
                    bool vl_ = (e0_ + lane < (size_t)n_edges);                 \
                    idx_s[wid][buf][lane]     = vl_ ? src[e0_ + lane] : 0;     \
                    idx_s[wid][buf][4 + lane] = vl_ ? dst[e0_ + lane] : 0;     \
                }                                                              \
            }                                                                  \
        } while (0)

    int cur = gwarp;
    if (cur < nb) STAGE(0, cur);
    CP_COMMIT();

    int pb = 0;
    for (; cur < nb; cur += wstride) {
        int nxt = cur + wstride;
        if (nxt < nb) STAGE(pb ^ 1, nxt);
        CP_COMMIT();
        CP_WAIT1();        // each lane: its own older group (current buf) done
        __syncwarp();      // cross-lane visibility of staged smem

        // ---- process: this half-warp handles edges 2*grp, 2*grp+1 ----
        int eA = 2 * grp;
        int eB = eA + 1;
        bool vA = ((size_t)cur * WEB + eA < (size_t)n_edges);
        bool vB = ((size_t)cur * WEB + eB < (size_t)n_edges);

        int siA = idx_s[wid][pb][eA],     diA = idx_s[wid][pb][4 + eA];
        int siB = idx_s[wid][pb][eB],     diB = idx_s[wid][pb][4 + eB];

        float4 a = *(const float4*)&ef_s[wid][pb][eA][4 * sl];
        float4 b = *(const float4*)&ef_s[wid][pb][eB][4 * sl];

        float4 hA = __ldg(hw4 + (size_t)siA * (F_OUT / 4) + sl);
        float4 hB = __ldg(hw4 + (size_t)siB * (F_OUT / 4) + sl);

        float a0 = __expf(a.x), a1 = __expf(a.y), a2 = __expf(a.z), a3 = __expf(a.w);
        float b0 = __expf(b.x), b1 = __expf(b.y), b2 = __expf(b.z), b3 = __expf(b.w);
        float sA = a0 + a1 + a2 + a3;
        float sB = b0 + b1 + b2 + b3;
        #pragma unroll
        for (int o = 8; o; o >>= 1) {
            sA += __shfl_xor_sync(0xffffffffu, sA, o);
            sB += __shfl_xor_sync(0xffffffffu, sB, o);
        }
        float iA = __fdividef(1.0f, sA);
        float iB = __fdividef(1.0f, sB);

        if (vA) {
            float* p = out + (size_t)diA * F_OUT + 4 * sl;
            asm volatile("red.global.add.v4.f32 [%0], {%1, %2, %3, %4};"
                         :: "l"(p), "f"(hA.x * a0 * iA), "f"(hA.y * a1 * iA),
                            "f"(hA.z * a2 * iA), "f"(hA.w * a3 * iA) : "memory");
        }
        if (vB) {
            float* p = out + (size_t)diB * F_OUT + 4 * sl;
            asm volatile("red.global.add.v4.f32 [%0], {%1, %2, %3, %4};"
                         :: "l"(p), "f"(hB.x * b0 * iB), "f"(hB.y * b1 * iB),
                            "f"(hB.z * b2 * iB), "f"(hB.w * b3 * iB) : "memory");
        }

        __syncwarp();      // buffer consumed before next stage overwrites it
        pb ^= 1;
    }
    #undef STAGE
}

// ---------------------------------------------------------------------------
extern "C" void kernel_launch(void* const* d_in, const int* in_sizes, int n_in,
                              void* d_out, int out_size) {
    const float* h    = (const float*)d_in[0];
    const float* ef   = (const float*)d_in[1];
    const float* w    = (const float*)d_in[2];
    const float* bias = (const float*)d_in[3];
    const int*   src  = (const int*)d_in[4];
    const int*   dst  = (const int*)d_in[5];
    float* out = (float*)d_out;

    int n_nodes = in_sizes[0] / F_IN;
    int n_edges = in_sizes[4];

    gemm_tc_kernel<<<(n_nodes + GR - 1) / GR, 128>>>(h, w, bias, out, n_nodes);

    int nwb = (n_edges + WEB - 1) / WEB;               // 4-edge warp-batches
    int blocks = (nwb + NWARPS - 1) / NWARPS;
    if (blocks > 1184) blocks = 1184;                  // 8 blocks/SM
    edge_kernel<<<blocks, 256>>>(ef, src, dst, out, n_edges);
}